// round 16
// baseline (speedup 1.0000x reference)
#include <cuda_runtime.h>
#include <cuda_fp16.h>
#include <math.h>
#include <stdint.h>

// ---------------- problem constants ----------------
#define DD     768
#define NTOK   171
#define BATCH  64
#define MROWS  (BATCH*NTOK)      // 10944
#define MPAD   11008             // 86*128
#define NPATCH 170
#define CROWS  (BATCH*NPATCH)    // 10880 = 85*128
#define KCONV  600
#define KCPAD  640
#define NHEAD  12
#define HDIM   64
#define DEPTH  12
#define EPS    1e-5f

// ---------------- scratch (device globals) ----------------
__device__ __half g_colh[CROWS * KCPAD];
__device__ __half g_coll[CROWS * KCPAD];
__device__ __half g_convWh[DD * KCPAD];
__device__ float g_h   [MROWS * DD];
__device__ float g_cls [BATCH * DD];
__device__ __half g_qkvh [MPAD * 3 * DD];
__device__ __half g_yf   [MPAD * DD];
__device__ __half g_af   [MPAD * DD];
__device__ __half g_bigf [MPAD * 4 * DD];
__device__ __half g_qkvWh[DEPTH * 3 * DD * DD];
__device__ __half g_projWh[DEPTH * DD * DD];
__device__ __half g_fc1Wh[DEPTH * 4 * DD * DD];
__device__ __half g_fc2Wh[DEPTH * 4 * DD * DD];

// ---------------- helpers ----------------
__device__ __forceinline__ uint32_t smem_u32(const void* p) {
    uint32_t a;
    asm("{ .reg .u64 t; cvta.to.shared.u64 t, %1; cvt.u32.u64 %0, t; }" : "=r"(a) : "l"(p));
    return a;
}
__device__ __forceinline__ void cp_async16(uint32_t dst, const void* src) {
    asm volatile("cp.async.cg.shared.global [%0], [%1], 16;"
                 :: "r"(dst), "l"(src) : "memory");
}
__device__ __forceinline__ void cp_commit() {
    asm volatile("cp.async.commit_group;" ::: "memory");
}
template <int N>
__device__ __forceinline__ void cp_wait() {
    asm volatile("cp.async.wait_group %0;" :: "n"(N) : "memory");
}
__device__ __forceinline__ void ldsm4(uint32_t* r, uint32_t addr) {
    asm volatile("ldmatrix.sync.aligned.m8n8.x4.shared.b16 {%0,%1,%2,%3}, [%4];"
                 : "=r"(r[0]), "=r"(r[1]), "=r"(r[2]), "=r"(r[3]) : "r"(addr));
}
__device__ __forceinline__ void mma_f16(float* c, const uint32_t* a, const uint32_t* b) {
    asm volatile(
        "mma.sync.aligned.m16n8k16.row.col.f32.f16.f16.f32 "
        "{%0,%1,%2,%3}, {%4,%5,%6,%7}, {%8,%9}, {%0,%1,%2,%3};"
        : "+f"(c[0]), "+f"(c[1]), "+f"(c[2]), "+f"(c[3])
        : "r"(a[0]), "r"(a[1]), "r"(a[2]), "r"(a[3]), "r"(b[0]), "r"(b[1]));
}
__device__ __forceinline__ void splith(float v, __half& hi, __half& lo) {
    hi = __float2half(v);
    lo = __float2half(v - __half2float(hi));
}
__device__ __forceinline__ uint32_t pack_h2(float a, float b) {
    __half2 h = __floats2half2_rn(a, b);
    return *(uint32_t*)&h;
}

// ---------------- fp16 GEMM: C = A @ Wh^T (BK=96, 2-stage, 2 CTAs/SM) ----------------
#define GSTR3 104                        // row stride (halves) = 208B; 208%128==80 -> conflict-free
#define TILE3B (128 * GSTR3 * 2)         // 26624 B
#define STG3 (2 * TILE3B)                // 53248 B per stage (A + W)
#define SMTOT1 (2 * STG3)                // 106496 B/CTA

template <bool OUTF16, bool GELU_, bool RES>
__global__ void __launch_bounds__(256, 2)
hmma_gemm(const __half* __restrict__ A, const __half* __restrict__ Wh,
          const float* __restrict__ bias, const float* __restrict__ res,
          float* __restrict__ Cf, __half* __restrict__ Ch,
          int Mvalid, int Ntot, int K) {
    extern __shared__ char dsm[];
    const uint32_t sb = smem_u32(dsm);

    const int tid = threadIdx.x;
    const int lane = tid & 31, wid = tid >> 5;
    const int wm = wid & 1, wn = wid >> 1;
    const int group = lane >> 2, tq = lane & 3;
    const int m0 = blockIdx.y * 128;
    const int n0 = blockIdx.x * 128;
    const int KT = K / 96;               // 8 (K=768) or 32 (K=3072)

    const __half* gA = A + (size_t)m0 * K;
    const __half* gWh = Wh + (size_t)n0 * K;

    float acc[4][4][4];
#pragma unroll
    for (int mi = 0; mi < 4; mi++)
#pragma unroll
        for (int ni = 0; ni < 4; ni++)
#pragma unroll
            for (int q = 0; q < 4; q++) acc[mi][ni][q] = 0.f;

    auto load_stage = [&](int kt, int st) {
        const size_t koff = (size_t)kt * 96;
        uint32_t base = sb + st * STG3;
#pragma unroll
        for (int i = 0; i < 6; i++) {
            int idx = tid + i * 256;
            int r = idx / 12, c = idx % 12;      // 128 rows x 12 chunks of 16B
            uint32_t so = (r * GSTR3 + c * 8) * 2;
            size_t go = (size_t)r * K + koff + c * 8;
            cp_async16(base + 0 * TILE3B + so, gA + go);
            cp_async16(base + 1 * TILE3B + so, gWh + go);
        }
        cp_commit();
    };

    const uint32_t arow = wm * 64 + (lane & 7) + ((lane >> 3) & 1) * 8;
    const uint32_t acol = (lane >> 4) * 8;
    const uint32_t aoff = (arow * GSTR3 + acol) * 2;
    const uint32_t brow = wn * 32 + (lane & 7) + (lane >> 4) * 8;
    const uint32_t bcol = ((lane >> 3) & 1) * 8;
    const uint32_t boff = (brow * GSTR3 + bcol) * 2;

    load_stage(0, 0);

#pragma unroll 2
    for (int kt = 0; kt < KT; kt++) {
        cp_wait<0>();
        __syncthreads();
        if (kt + 1 < KT) load_stage(kt + 1, (kt + 1) & 1);

        const uint32_t stbase = sb + (kt & 1) * STG3;
        const uint32_t aA = stbase + aoff;
        const uint32_t bH = stbase + TILE3B + boff;

#pragma unroll
        for (int ks = 0; ks < 6; ks++) {
            const uint32_t kadd = ks * 32;   // 16 halves
            uint32_t af[16], bh[8];
#pragma unroll
            for (int mi = 0; mi < 4; mi++)
                ldsm4(af + mi * 4, aA + mi * (16 * GSTR3 * 2) + kadd);
#pragma unroll
            for (int nj = 0; nj < 2; nj++)
                ldsm4(bh + nj * 4, bH + nj * (16 * GSTR3 * 2) + kadd);
#pragma unroll
            for (int mi = 0; mi < 4; mi++)
#pragma unroll
                for (int ni = 0; ni < 4; ni++)
                    mma_f16(acc[mi][ni], af + mi * 4, bh + ni * 2);
        }
    }

#pragma unroll
    for (int mi = 0; mi < 4; mi++) {
#pragma unroll
        for (int rr = 0; rr < 2; rr++) {
            int m = m0 + wm * 64 + mi * 16 + group + rr * 8;
            if (m >= Mvalid) continue;
#pragma unroll
            for (int ni = 0; ni < 4; ni++) {
                int n = n0 + wn * 32 + ni * 8 + tq * 2;
                float v0 = acc[mi][ni][rr * 2 + 0] + __ldg(bias + n);
                float v1 = acc[mi][ni][rr * 2 + 1] + __ldg(bias + n + 1);
                if (GELU_) {
                    v0 = 0.5f * v0 * (1.f + erff(v0 * 0.70710678118654752f));
                    v1 = 0.5f * v1 * (1.f + erff(v1 * 0.70710678118654752f));
                }
                if (RES) {
                    float2 rv = *(const float2*)(res + (size_t)m * Ntot + n);
                    v0 += rv.x; v1 += rv.y;
                }
                if (OUTF16) {
                    __half2 h2 = __floats2half2_rn(v0, v1);
                    *(__half2*)(Ch + (size_t)m * Ntot + n) = h2;
                } else {
                    *(float2*)(Cf + (size_t)m * Ntot + n) = make_float2(v0, v1);
                }
            }
        }
    }
}

// ---------------- conv GEMM (BK=32, split-A 2-product; unchanged) ----------------
#define GSTR 40
#define TILEB (128 * GSTR * 2)
#define CSTG (3 * TILEB)
#define CSMTOT (3 * CSTG)     // 92160 B/CTA

__global__ void __launch_bounds__(256, 2)
conv_gemm(const __half* __restrict__ Ah, const __half* __restrict__ Al,
          const __half* __restrict__ Wh, const float* __restrict__ bias,
          const float* __restrict__ pos, float* __restrict__ hout) {
    extern __shared__ char dsm[];
    const uint32_t sb = smem_u32(dsm);
    const int K = KCPAD, KT = KCPAD / 32;  // 20

    const int tid = threadIdx.x;
    const int lane = tid & 31, wid = tid >> 5;
    const int wm = wid & 1, wn = wid >> 1;
    const int group = lane >> 2, tq = lane & 3;
    const int m0 = blockIdx.y * 128;
    const int n0 = blockIdx.x * 128;

    const __half* gAh = Ah + (size_t)m0 * K;
    const __half* gAl = Al + (size_t)m0 * K;
    const __half* gWh = Wh + (size_t)n0 * K;

    float acc[4][4][4];
#pragma unroll
    for (int mi = 0; mi < 4; mi++)
#pragma unroll
        for (int ni = 0; ni < 4; ni++)
#pragma unroll
            for (int q = 0; q < 4; q++) acc[mi][ni][q] = 0.f;

    const int lr = tid >> 2;
    const int lc = tid & 3;

    auto load_stage = [&](int kt, int st) {
        const size_t koff = (size_t)kt * 32;
        uint32_t base = sb + st * CSTG;
#pragma unroll
        for (int i = 0; i < 2; i++) {
            int r = lr + i * 64;
            uint32_t so = (r * GSTR + lc * 8) * 2;
            size_t go = (size_t)r * K + koff + lc * 8;
            cp_async16(base + 0 * TILEB + so, gAh + go);
            cp_async16(base + 1 * TILEB + so, gAl + go);
            cp_async16(base + 2 * TILEB + so, gWh + go);
        }
        cp_commit();
    };

    const uint32_t arow = wm * 64 + (lane & 7) + ((lane >> 3) & 1) * 8;
    const uint32_t acol = (lane >> 4) * 8;
    const uint32_t aoff = (arow * GSTR + acol) * 2;
    const uint32_t brow = wn * 32 + (lane & 7) + (lane >> 4) * 8;
    const uint32_t bcol = ((lane >> 3) & 1) * 8;
    const uint32_t boff = (brow * GSTR + bcol) * 2;

    load_stage(0, 0);
    load_stage(1, 1);

#pragma unroll 1
    for (int kt = 0; kt < KT; kt++) {
        if (kt + 1 < KT) cp_wait<1>();
        else             cp_wait<0>();
        __syncthreads();

        const uint32_t stbase = sb + (kt % 3) * CSTG;
        const uint32_t aH = stbase + aoff;
        const uint32_t aL = stbase + TILEB + aoff;
        const uint32_t bH = stbase + 2 * TILEB + boff;

#pragma unroll
        for (int ks = 0; ks < 2; ks++) {
            const uint32_t kadd = ks * 32;
            uint32_t afh[16], afl[16], bh[8];
#pragma unroll
            for (int mi = 0; mi < 4; mi++) {
                ldsm4(afh + mi * 4, aH + mi * (16 * GSTR * 2) + kadd);
                ldsm4(afl + mi * 4, aL + mi * (16 * GSTR * 2) + kadd);
            }
#pragma unroll
            for (int nj = 0; nj < 2; nj++)
                ldsm4(bh + nj * 4, bH + nj * (16 * GSTR * 2) + kadd);
#pragma unroll
            for (int mi = 0; mi < 4; mi++)
#pragma unroll
                for (int ni = 0; ni < 4; ni++)
                    mma_f16(acc[mi][ni], afh + mi * 4, bh + ni * 2);
#pragma unroll
            for (int mi = 0; mi < 4; mi++)
#pragma unroll
                for (int ni = 0; ni < 4; ni++)
                    mma_f16(acc[mi][ni], afl + mi * 4, bh + ni * 2);
        }

        if (kt + 2 < KT) load_stage(kt + 2, (kt + 2) % 3);
    }

#pragma unroll
    for (int mi = 0; mi < 4; mi++) {
#pragma unroll
        for (int rr = 0; rr < 2; rr++) {
            int m = m0 + wm * 64 + mi * 16 + group + rr * 8;
            int b = m / NPATCH, p = m % NPATCH;
            size_t row = (size_t)b * NTOK + p + 1;
            const float* pr = pos + (size_t)(p + 1) * DD;
#pragma unroll
            for (int ni = 0; ni < 4; ni++) {
                int n = n0 + wn * 32 + ni * 8 + tq * 2;
                float v0 = acc[mi][ni][rr * 2 + 0] + bias[n] + pr[n];
                float v1 = acc[mi][ni][rr * 2 + 1] + bias[n + 1] + pr[n + 1];
                *(float2*)(hout + row * DD + n) = make_float2(v0, v1);
            }
        }
    }
}

// ---------------- im2col -> split fp16 (padded K=640) ----------------
__global__ void im2col_split(const float* __restrict__ x,
                             __half* __restrict__ colh, __half* __restrict__ coll) {
    int idx = blockIdx.x * blockDim.x + threadIdx.x;
    if (idx >= CROWS * KCPAD) return;
    int r = idx / KCPAD, c = idx % KCPAD;
    float v = 0.f;
    if (c < KCONV) {
        int b = r / NPATCH, p = r % NPATCH;
        int chn = c / 100, rem = c % 100;
        int kh = rem / 10, kw = rem % 10;
        int phh = p / 34, pw = p % 34;
        v = x[((b * 6 + chn) * 50 + phh * 10 + kh) * 345 + pw * 10 + kw];
    }
    __half hi, lo;
    splith(v, hi, lo);
    colh[idx] = hi;
    coll[idx] = lo;
}

// ---------------- conv weight -> fp16 (padded K=640) ----------------
__global__ void convw_prep(const float* __restrict__ w, __half* __restrict__ wh) {
    int idx = blockIdx.x * blockDim.x + threadIdx.x;
    if (idx >= DD * KCPAD) return;
    int d = idx / KCPAD, k = idx % KCPAD;
    wh[idx] = __float2half(k < KCONV ? w[d * KCONV + k] : 0.f);
}

// ---------------- cls token rows ----------------
__global__ void cls_fill(const float* __restrict__ cls, const float* __restrict__ pos,
                         float* __restrict__ h) {
    int idx = blockIdx.x * blockDim.x + threadIdx.x;
    if (idx >= BATCH * DD) return;
    int b = idx / DD, d = idx % DD;
    h[(size_t)b * NTOK * DD + d] = cls[d] + pos[d];
}

// ---------------- weight transpose -> fp16 (hi only) ----------------
__global__ void transpose_hi(const float* __restrict__ W, __half* __restrict__ Wh,
                             int R, int C) {
    __shared__ float t[32][33];
    int z = blockIdx.z;
    const float* Wz = W + (size_t)z * R * C;
    __half* Whz = Wh + (size_t)z * R * C;
    int c0 = blockIdx.x * 32, r0 = blockIdx.y * 32;
    int x = threadIdx.x, y = threadIdx.y;
#pragma unroll
    for (int i = 0; i < 32; i += 8)
        t[y + i][x] = Wz[(size_t)(r0 + y + i) * C + c0 + x];
    __syncthreads();
#pragma unroll
    for (int i = 0; i < 32; i += 8)
        Whz[(size_t)(c0 + y + i) * R + r0 + x] = __float2half(t[x][y + i]);
}

// ---------------- LayerNorm fp32 -> fp16 ----------------
__global__ void ln_f16_kernel(const float* __restrict__ X, const float* __restrict__ w,
                              const float* __restrict__ b, __half* __restrict__ Y) {
    int row = blockIdx.x;
    int tid = threadIdx.x;
    const float* xr = X + (size_t)row * DD;
    float v0 = xr[tid], v1 = xr[tid + 256], v2 = xr[tid + 512];
    float s = v0 + v1 + v2;
    float q = v0 * v0 + v1 * v1 + v2 * v2;
    int lane = tid & 31, warp = tid >> 5;
#pragma unroll
    for (int off = 16; off; off >>= 1) {
        s += __shfl_down_sync(0xffffffffu, s, off);
        q += __shfl_down_sync(0xffffffffu, q, off);
    }
    __shared__ float sa[8], sbm[8];
    if (lane == 0) { sa[warp] = s; sbm[warp] = q; }
    __syncthreads();
    if (warp == 0) {
        s = (lane < 8) ? sa[lane] : 0.f;
        q = (lane < 8) ? sbm[lane] : 0.f;
#pragma unroll
        for (int off = 4; off; off >>= 1) {
            s += __shfl_down_sync(0xffffffffu, s, off);
            q += __shfl_down_sync(0xffffffffu, q, off);
        }
        if (lane == 0) { sa[0] = s; sbm[0] = q; }
    }
    __syncthreads();
    float mean = sa[0] * (1.f / DD);
    float var = sbm[0] * (1.f / DD) - mean * mean;
    float inv = rsqrtf(var + EPS);
    __half* yr = Y + (size_t)row * DD;
    yr[tid]       = __float2half((v0 - mean) * inv * w[tid]       + b[tid]);
    yr[tid + 256] = __float2half((v1 - mean) * inv * w[tid + 256] + b[tid + 256]);
    yr[tid + 512] = __float2half((v2 - mean) * inv * w[tid + 512] + b[tid + 512]);
}

// ---------------- LayerNorm fp32 -> fp32 (final, cls rows) ----------------
__global__ void ln_kernel(const float* __restrict__ X, const float* __restrict__ w,
                          const float* __restrict__ b, float* __restrict__ Y, int row_mul) {
    int row_in = blockIdx.x * row_mul;
    int row_out = blockIdx.x;
    int tid = threadIdx.x;
    const float* xr = X + (size_t)row_in * DD;
    float v0 = xr[tid], v1 = xr[tid + 256], v2 = xr[tid + 512];
    float s = v0 + v1 + v2;
    float q = v0 * v0 + v1 * v1 + v2 * v2;
    int lane = tid & 31, warp = tid >> 5;
#pragma unroll
    for (int off = 16; off; off >>= 1) {
        s += __shfl_down_sync(0xffffffffu, s, off);
        q += __shfl_down_sync(0xffffffffu, q, off);
    }
    __shared__ float sa[8], sbm[8];
    if (lane == 0) { sa[warp] = s; sbm[warp] = q; }
    __syncthreads();
    if (warp == 0) {
        s = (lane < 8) ? sa[lane] : 0.f;
        q = (lane < 8) ? sbm[lane] : 0.f;
#pragma unroll
        for (int off = 4; off; off >>= 1) {
            s += __shfl_down_sync(0xffffffffu, s, off);
            q += __shfl_down_sync(0xffffffffu, q, off);
        }
        if (lane == 0) { sa[0] = s; sbm[0] = q; }
    }
    __syncthreads();
    float mean = sa[0] * (1.f / DD);
    float var = sbm[0] * (1.f / DD) - mean * mean;
    float inv = rsqrtf(var + EPS);
    float* yr = Y + (size_t)row_out * DD;
    yr[tid]       = (v0 - mean) * inv * w[tid]       + b[tid];
    yr[tid + 256] = (v1 - mean) * inv * w[tid + 256] + b[tid + 256];
    yr[tid + 512] = (v2 - mean) * inv * w[tid + 512] + b[tid + 512];
}

// ---------------- MMA attention (fp16 qkv in, single product, 11 warps) ----------------
#define NTOKP 176
#define ASTR 72
#define VSTR 184
#define SA_QH 0
#define SA_KH (SA_QH + NTOKP*ASTR*2)
#define SA_VH (SA_KH + NTOKP*ASTR*2)
#define ATTN_SMEM (SA_VH + 64*VSTR*2)   // 74240 B
#define ATHREADS 352

__global__ void __launch_bounds__(ATHREADS, 1)
attn_mma_kernel(const __half* __restrict__ qkv, __half* __restrict__ out) {
    extern __shared__ char asmem[];
    const uint32_t sb = smem_u32(asmem);
    __half* QH = (__half*)(asmem + SA_QH);
    __half* KH = (__half*)(asmem + SA_KH);
    __half* VH = (__half*)(asmem + SA_VH);

    const int bh = blockIdx.x;
    const int b = bh / NHEAD, hh = bh % NHEAD;
    const int tid = threadIdx.x;
    const int lane = tid & 31, wid = tid >> 5;
    const int group = lane >> 2, tq = lane & 3;
    const size_t base = (size_t)b * NTOK * (3 * DD) + hh * HDIM;

    for (int idx = tid; idx < NTOKP * 64; idx += ATHREADS) {
        int row = idx >> 6, d = idx & 63;
        __half qv = __float2half(0.f), kv = qv, vv = qv;
        if (row < NTOK) {
            size_t o = base + (size_t)row * (3 * DD) + d;
            qv = qkv[o]; kv = qkv[o + DD]; vv = qkv[o + 2 * DD];
        }
        QH[row * ASTR + d] = qv;
        KH[row * ASTR + d] = kv;
        VH[d * VSTR + row] = vv;
    }
    __syncthreads();

    const uint32_t a_r = (lane & 7) + ((lane >> 3) & 1) * 8;
    const uint32_t a_c = (lane >> 4) * 8;
    const uint32_t b_r = (lane & 7) + (lane >> 4) * 8;
    const uint32_t b_c = ((lane >> 3) & 1) * 8;

    if (wid < 11) {
        const int m0 = wid * 16;

        uint32_t aq[4][4];
#pragma unroll
        for (int k = 0; k < 4; k++) {
            uint32_t off = ((m0 + a_r) * ASTR + a_c + k * 16) * 2;
            ldsm4(aq[k], sb + SA_QH + off);
        }

        float s[22][4];
#pragma unroll
        for (int j = 0; j < 22; j++)
#pragma unroll
            for (int q = 0; q < 4; q++) s[j][q] = 0.f;

#pragma unroll
        for (int nj = 0; nj < 11; nj++) {
            const int n0 = nj * 16;
#pragma unroll
            for (int k = 0; k < 4; k++) {
                uint32_t bkh[4];
                uint32_t off = ((n0 + b_r) * ASTR + b_c + k * 16) * 2;
                ldsm4(bkh, sb + SA_KH + off);
                mma_f16(s[2 * nj],     aq[k], bkh);
                mma_f16(s[2 * nj + 1], aq[k], bkh + 2);
            }
        }

        {
            int c0 = 168 + tq * 2;
            if (c0 >= NTOK)     { s[21][0] = -1e30f; s[21][2] = -1e30f; }
            if (c0 + 1 >= NTOK) { s[21][1] = -1e30f; s[21][3] = -1e30f; }
        }

        float mx0 = -1e30f, mx1 = -1e30f;
#pragma unroll
        for (int j = 0; j < 22; j++) {
            mx0 = fmaxf(mx0, fmaxf(s[j][0], s[j][1]));
            mx1 = fmaxf(mx1, fmaxf(s[j][2], s[j][3]));
        }
        mx0 = fmaxf(mx0, __shfl_xor_sync(0xffffffffu, mx0, 1));
        mx0 = fmaxf(mx0, __shfl_xor_sync(0xffffffffu, mx0, 2));
        mx1 = fmaxf(mx1, __shfl_xor_sync(0xffffffffu, mx1, 1));
        mx1 = fmaxf(mx1, __shfl_xor_sync(0xffffffffu, mx1, 2));

        float rs0 = 0.f, rs1 = 0.f;
#pragma unroll
        for (int j = 0; j < 22; j++) {
            s[j][0] = __expf((s[j][0] - mx0) * 0.125f);
            s[j][1] = __expf((s[j][1] - mx0) * 0.125f);
            s[j][2] = __expf((s[j][2] - mx1) * 0.125f);
            s[j][3] = __expf((s[j][3] - mx1) * 0.125f);
            rs0 += s[j][0] + s[j][1];
            rs1 += s[j][2] + s[j][3];
        }
        rs0 += __shfl_xor_sync(0xffffffffu, rs0, 1);
        rs0 += __shfl_xor_sync(0xffffffffu, rs0, 2);
        rs1 += __shfl_xor_sync(0xffffffffu, rs1, 1);
        rs1 += __shfl_xor_sync(0xffffffffu, rs1, 2);

        float o[8][4];
#pragma unroll
        for (int j = 0; j < 8; j++)
#pragma unroll
            for (int q = 0; q < 4; q++) o[j][q] = 0.f;

#pragma unroll
        for (int kt = 0; kt < 11; kt++) {
            uint32_t ap[4];
#pragma unroll
            for (int half = 0; half < 2; half++) {
                const float* sv = s[2 * kt + half];
                ap[2 * half]     = pack_h2(sv[0], sv[1]);
                ap[2 * half + 1] = pack_h2(sv[2], sv[3]);
            }
#pragma unroll
            for (int dj = 0; dj < 4; dj++) {
                const int d0 = dj * 16;
                uint32_t bvh[4];
                uint32_t off = ((d0 + b_r) * VSTR + b_c + kt * 16) * 2;
                ldsm4(bvh, sb + SA_VH + off);
                mma_f16(o[2 * dj],     ap, bvh);
                mma_f16(o[2 * dj + 1], ap, bvh + 2);
            }
        }

        const float i0 = 1.f / rs0, i1 = 1.f / rs1;
        const int r0 = m0 + group, r1 = r0 + 8;
#pragma unroll
        for (int j = 0; j < 8; j++) {
            int d = 8 * j + tq * 2;
            if (r0 < NTOK) {
                __half2 hv = __floats2half2_rn(o[j][0] * i0, o[j][1] * i0);
                *(__half2*)(out + (size_t)(b * NTOK + r0) * DD + hh * HDIM + d) = hv;
            }
            if (r1 < NTOK) {
                __half2 hv = __floats2half2_rn(o[j][2] * i1, o[j][3] * i1);
                *(__half2*)(out + (size_t)(b * NTOK + r1) * DD + hh * HDIM + d) = hv;
            }
        }
    }
}

// ---------------- head ----------------
__global__ void head_kernel(const float* __restrict__ cls, const float* __restrict__ hw,
                            const float* __restrict__ hb, float* __restrict__ out) {
    int b = blockIdx.x;
    int tid = threadIdx.x;
    float a0 = 0.f, a1 = 0.f, a2 = 0.f;
    for (int d = tid; d < DD; d += 256) {
        float v = cls[b * DD + d];
        a0 += v * hw[d * 3 + 0];
        a1 += v * hw[d * 3 + 1];
        a2 += v * hw[d * 3 + 2];
    }
    int lane = tid & 31, warp = tid >> 5;
#pragma unroll
    for (int off = 16; off; off >>= 1) {
        a0 += __shfl_down_sync(0xffffffffu, a0, off);
        a1 += __shfl_down_sync(0xffffffffu, a1, off);
        a2 += __shfl_down_sync(0xffffffffu, a2, off);
    }
    __shared__ float s0[8], s1[8], s2[8];
    if (lane == 0) { s0[warp] = a0; s1[warp] = a1; s2[warp] = a2; }
    __syncthreads();
    if (warp == 0 && lane < 8) {
        a0 = s0[lane]; a1 = s1[lane]; a2 = s2[lane];
#pragma unroll
        for (int off = 4; off; off >>= 1) {
            a0 += __shfl_down_sync(0x000000ffu, a0, off);
            a1 += __shfl_down_sync(0x000000ffu, a1, off);
            a2 += __shfl_down_sync(0x000000ffu, a2, off);
        }
        if (lane == 0) {
            out[b * 3 + 0] = a0 + hb[0];
            out[b * 3 + 1] = a1 + hb[1];
            out[b * 3 + 2] = a2 + hb[2];
        }
    }
}

// ---------------- launcher ----------------
extern "C" void kernel_launch(void* const* d_in, const int* in_sizes, int n_in,
                              void* d_out, int out_size) {
    const float* x        = (const float*)d_in[0];
    const float* conv_w   = (const float*)d_in[1];
    const float* conv_b   = (const float*)d_in[2];
    const float* cls_tok  = (const float*)d_in[3];
    const float* pos      = (const float*)d_in[4];
    const float* ln1_w    = (const float*)d_in[5];
    const float* ln1_b    = (const float*)d_in[6];
    const float* qkv_w    = (const float*)d_in[7];
    const float* qkv_b    = (const float*)d_in[8];
    const float* proj_w   = (const float*)d_in[9];
    const float* proj_b   = (const float*)d_in[10];
    const float* ln2_w    = (const float*)d_in[11];
    const float* ln2_b    = (const float*)d_in[12];
    const float* fc1_w    = (const float*)d_in[13];
    const float* fc1_b    = (const float*)d_in[14];
    const float* fc2_w    = (const float*)d_in[15];
    const float* fc2_b    = (const float*)d_in[16];
    const float* norm_w   = (const float*)d_in[17];
    const float* norm_b   = (const float*)d_in[18];
    const float* head_w   = (const float*)d_in[19];
    const float* head_b   = (const float*)d_in[20];
    float* out = (float*)d_out;

    float *h, *clsb;
    __half *colh, *coll, *convWh, *qkvh, *yf, *af, *bigf;
    __half *qkvWh, *projWh, *fc1Wh, *fc2Wh;
    cudaGetSymbolAddress((void**)&colh, g_colh);
    cudaGetSymbolAddress((void**)&coll, g_coll);
    cudaGetSymbolAddress((void**)&convWh, g_convWh);
    cudaGetSymbolAddress((void**)&h, g_h);
    cudaGetSymbolAddress((void**)&clsb, g_cls);
    cudaGetSymbolAddress((void**)&qkvh, g_qkvh);
    cudaGetSymbolAddress((void**)&yf, g_yf);
    cudaGetSymbolAddress((void**)&af, g_af);
    cudaGetSymbolAddress((void**)&bigf, g_bigf);
    cudaGetSymbolAddress((void**)&qkvWh, g_qkvWh);
    cudaGetSymbolAddress((void**)&projWh, g_projWh);
    cudaGetSymbolAddress((void**)&fc1Wh, g_fc1Wh);
    cudaGetSymbolAddress((void**)&fc2Wh, g_fc2Wh);

    cudaFuncSetAttribute(attn_mma_kernel, cudaFuncAttributeMaxDynamicSharedMemorySize, ATTN_SMEM);
    cudaFuncSetAttribute(hmma_gemm<true, false, false>, cudaFuncAttributeMaxDynamicSharedMemorySize, SMTOT1);
    cudaFuncSetAttribute(hmma_gemm<false, false, true>, cudaFuncAttributeMaxDynamicSharedMemorySize, SMTOT1);
    cudaFuncSetAttribute(hmma_gemm<true, true, false>, cudaFuncAttributeMaxDynamicSharedMemorySize, SMTOT1);
    cudaFuncSetAttribute(conv_gemm, cudaFuncAttributeMaxDynamicSharedMemorySize, CSMTOT);

    // weight prep
    transpose_hi<<<dim3(3 * DD / 32, DD / 32, DEPTH), dim3(32, 8)>>>(qkv_w, qkvWh, DD, 3 * DD);
    transpose_hi<<<dim3(DD / 32, DD / 32, DEPTH), dim3(32, 8)>>>(proj_w, projWh, DD, DD);
    transpose_hi<<<dim3(4 * DD / 32, DD / 32, DEPTH), dim3(32, 8)>>>(fc1_w, fc1Wh, DD, 4 * DD);
    transpose_hi<<<dim3(DD / 32, 4 * DD / 32, DEPTH), dim3(32, 8)>>>(fc2_w, fc2Wh, 4 * DD, DD);
    convw_prep<<<(DD * KCPAD + 255) / 256, 256>>>(conv_w, convWh);

    // patch embed (fp16 2-product, fused pos-embed + assemble)
    im2col_split<<<(CROWS * KCPAD + 255) / 256, 256>>>(x, colh, coll);
    cls_fill<<<(BATCH * DD + 255) / 256, 256>>>(cls_tok, pos, h);
    conv_gemm<<<dim3(DD / 128, CROWS / 128), 256, CSMTOT>>>(colh, coll, convWh, conv_b, pos, h);

    const int MT = MPAD / 128;  // 86
    for (int i = 0; i < DEPTH; i++) {
        ln_f16_kernel<<<MROWS, 256>>>(h, ln1_w + (size_t)i * DD, ln1_b + (size_t)i * DD, yf);
        hmma_gemm<true, false, false><<<dim3(3 * DD / 128, MT), 256, SMTOT1>>>(
            yf, qkvWh + (size_t)i * 3 * DD * DD,
            qkv_b + (size_t)i * 3 * DD, nullptr, nullptr, qkvh, MROWS, 3 * DD, DD);
        attn_mma_kernel<<<BATCH * NHEAD, ATHREADS, ATTN_SMEM>>>(qkvh, af);
        hmma_gemm<false, false, true><<<dim3(DD / 128, MT), 256, SMTOT1>>>(
            af, projWh + (size_t)i * DD * DD,
            proj_b + (size_t)i * DD, h, h, nullptr, MROWS, DD, DD);
        ln_f16_kernel<<<MROWS, 256>>>(h, ln2_w + (size_t)i * DD, ln2_b + (size_t)i * DD, yf);
        hmma_gemm<true, true, false><<<dim3(4 * DD / 128, MT), 256, SMTOT1>>>(
            yf, fc1Wh + (size_t)i * 4 * DD * DD,
            fc1_b + (size_t)i * 4 * DD, nullptr, nullptr, bigf, MROWS, 4 * DD, DD);
        hmma_gemm<false, false, true><<<dim3(DD / 128, MT), 256, SMTOT1>>>(
            bigf, fc2Wh + (size_t)i * 4 * DD * DD,
            fc2_b + (size_t)i * DD, h, h, nullptr, MROWS, DD, 4 * DD);
    }

    ln_kernel<<<BATCH, 256>>>(h, norm_w, norm_b, clsb, NTOK);
    head_kernel<<<BATCH, 256>>>(clsb, head_w, head_b, out);
}

// round 17
// speedup vs baseline: 1.0985x; 1.0985x over previous
#include <cuda_runtime.h>
#include <cuda_fp16.h>
#include <math.h>
#include <stdint.h>

// ---------------- problem constants ----------------
#define DD     768
#define NTOK   171
#define BATCH  64
#define MROWS  (BATCH*NTOK)      // 10944
#define MPAD   11008             // 86*128
#define NPATCH 170
#define CROWS  (BATCH*NPATCH)    // 10880 = 85*128
#define KCONV  600
#define KCPAD  640
#define NHEAD  12
#define HDIM   64
#define DEPTH  12
#define EPS    1e-5f

// ---------------- scratch (device globals) ----------------
__device__ __half g_colh[CROWS * KCPAD];
__device__ __half g_coll[CROWS * KCPAD];
__device__ __half g_convWh[DD * KCPAD];
__device__ float g_h   [MROWS * DD];
__device__ float g_cls [BATCH * DD];
__device__ __half g_qkvh [MPAD * 3 * DD];
__device__ __half g_yf   [MPAD * DD];
__device__ __half g_af   [MPAD * DD];
__device__ __half g_bigf [MPAD * 4 * DD];
__device__ __half g_qkvWh[DEPTH * 3 * DD * DD];
__device__ __half g_projWh[DEPTH * DD * DD];
__device__ __half g_fc1Wh[DEPTH * 4 * DD * DD];
__device__ __half g_fc2Wh[DEPTH * 4 * DD * DD];

// ---------------- helpers ----------------
__device__ __forceinline__ uint32_t smem_u32(const void* p) {
    uint32_t a;
    asm("{ .reg .u64 t; cvta.to.shared.u64 t, %1; cvt.u32.u64 %0, t; }" : "=r"(a) : "l"(p));
    return a;
}
__device__ __forceinline__ void cp_async16(uint32_t dst, const void* src) {
    asm volatile("cp.async.cg.shared.global [%0], [%1], 16;"
                 :: "r"(dst), "l"(src) : "memory");
}
__device__ __forceinline__ void cp_commit() {
    asm volatile("cp.async.commit_group;" ::: "memory");
}
template <int N>
__device__ __forceinline__ void cp_wait() {
    asm volatile("cp.async.wait_group %0;" :: "n"(N) : "memory");
}
__device__ __forceinline__ void ldsm4(uint32_t* r, uint32_t addr) {
    asm volatile("ldmatrix.sync.aligned.m8n8.x4.shared.b16 {%0,%1,%2,%3}, [%4];"
                 : "=r"(r[0]), "=r"(r[1]), "=r"(r[2]), "=r"(r[3]) : "r"(addr));
}
__device__ __forceinline__ void mma_f16(float* c, const uint32_t* a, const uint32_t* b) {
    asm volatile(
        "mma.sync.aligned.m16n8k16.row.col.f32.f16.f16.f32 "
        "{%0,%1,%2,%3}, {%4,%5,%6,%7}, {%8,%9}, {%0,%1,%2,%3};"
        : "+f"(c[0]), "+f"(c[1]), "+f"(c[2]), "+f"(c[3])
        : "r"(a[0]), "r"(a[1]), "r"(a[2]), "r"(a[3]), "r"(b[0]), "r"(b[1]));
}
__device__ __forceinline__ void splith(float v, __half& hi, __half& lo) {
    hi = __float2half(v);
    lo = __float2half(v - __half2float(hi));
}
__device__ __forceinline__ uint32_t pack_h2(float a, float b) {
    __half2 h = __floats2half2_rn(a, b);
    return *(uint32_t*)&h;
}

// ---------------- fp16 GEMM: C = A @ Wh^T (BK=64, 3 stages, unroll-3 ring; R15) ----------------
#define GSTR2 72                         // row stride (halves) = 144B
#define TILE2B (128 * GSTR2 * 2)         // 18432 B
#define STG2 (2 * TILE2B)                // 36864 B per stage
#define NST2 3
#define SMTOT1 (NST2 * STG2)             // 110592 B/CTA

template <bool OUTF16, bool GELU_, bool RES>
__global__ void __launch_bounds__(256, 2)
hmma_gemm(const __half* __restrict__ A, const __half* __restrict__ Wh,
          const float* __restrict__ bias, const float* __restrict__ res,
          float* __restrict__ Cf, __half* __restrict__ Ch,
          int Mvalid, int Ntot, int K) {
    extern __shared__ char dsm[];
    const uint32_t sb = smem_u32(dsm);

    const int tid = threadIdx.x;
    const int lane = tid & 31, wid = tid >> 5;
    const int wm = wid & 1, wn = wid >> 1;
    const int group = lane >> 2, tq = lane & 3;
    const int m0 = blockIdx.y * 128;
    const int n0 = blockIdx.x * 128;
    const int KT = K >> 6;               // 12 or 48; always %3==0

    const __half* gA = A + (size_t)m0 * K;
    const __half* gWh = Wh + (size_t)n0 * K;

    float acc[4][4][4];
#pragma unroll
    for (int mi = 0; mi < 4; mi++)
#pragma unroll
        for (int ni = 0; ni < 4; ni++)
#pragma unroll
            for (int q = 0; q < 4; q++) acc[mi][ni][q] = 0.f;

    const int lr = tid >> 3;             // 0..31
    const int lc = tid & 7;              // 16B chunk 0..7

    auto load_stage = [&](int kt, int st) {
        const size_t koff = (size_t)kt * 64;
        uint32_t base = sb + st * STG2;
#pragma unroll
        for (int i = 0; i < 4; i++) {
            int r = lr + i * 32;
            uint32_t so = (r * GSTR2 + lc * 8) * 2;
            size_t go = (size_t)r * K + koff + lc * 8;
            cp_async16(base + 0 * TILE2B + so, gA + go);
            cp_async16(base + 1 * TILE2B + so, gWh + go);
        }
        cp_commit();
    };

    const uint32_t arow = wm * 64 + (lane & 7) + ((lane >> 3) & 1) * 8;
    const uint32_t acol = (lane >> 4) * 8;
    const uint32_t aoff = (arow * GSTR2 + acol) * 2;
    const uint32_t brow = wn * 32 + (lane & 7) + (lane >> 4) * 8;
    const uint32_t bcol = ((lane >> 3) & 1) * 8;
    const uint32_t boff = (brow * GSTR2 + bcol) * 2;

    load_stage(0, 0);
    if (KT > 1) load_stage(1, 1);

#pragma unroll 3
    for (int kt = 0; kt < KT; kt++) {
        if (kt + 1 < KT) cp_wait<1>();
        else             cp_wait<0>();
        __syncthreads();

        const uint32_t stbase = sb + (kt % 3) * STG2;
        const uint32_t aA = stbase + aoff;
        const uint32_t bH = stbase + TILE2B + boff;

#pragma unroll
        for (int ks = 0; ks < 4; ks++) {
            const uint32_t kadd = ks * 32;
            uint32_t af[16], bh[8];
#pragma unroll
            for (int mi = 0; mi < 4; mi++)
                ldsm4(af + mi * 4, aA + mi * (16 * GSTR2 * 2) + kadd);
#pragma unroll
            for (int nj = 0; nj < 2; nj++)
                ldsm4(bh + nj * 4, bH + nj * (16 * GSTR2 * 2) + kadd);
#pragma unroll
            for (int mi = 0; mi < 4; mi++)
#pragma unroll
                for (int ni = 0; ni < 4; ni++)
                    mma_f16(acc[mi][ni], af + mi * 4, bh + ni * 2);
        }

        if (kt + 2 < KT) load_stage(kt + 2, (kt + 2) % 3);
    }

#pragma unroll
    for (int mi = 0; mi < 4; mi++) {
#pragma unroll
        for (int rr = 0; rr < 2; rr++) {
            int m = m0 + wm * 64 + mi * 16 + group + rr * 8;
            if (m >= Mvalid) continue;
#pragma unroll
            for (int ni = 0; ni < 4; ni++) {
                int n = n0 + wn * 32 + ni * 8 + tq * 2;
                float v0 = acc[mi][ni][rr * 2 + 0] + __ldg(bias + n);
                float v1 = acc[mi][ni][rr * 2 + 1] + __ldg(bias + n + 1);
                if (GELU_) {
                    v0 = 0.5f * v0 * (1.f + erff(v0 * 0.70710678118654752f));
                    v1 = 0.5f * v1 * (1.f + erff(v1 * 0.70710678118654752f));
                }
                if (RES) {
                    float2 rv = *(const float2*)(res + (size_t)m * Ntot + n);
                    v0 += rv.x; v1 += rv.y;
                }
                if (OUTF16) {
                    __half2 h2 = __floats2half2_rn(v0, v1);
                    *(__half2*)(Ch + (size_t)m * Ntot + n) = h2;
                } else {
                    *(float2*)(Cf + (size_t)m * Ntot + n) = make_float2(v0, v1);
                }
            }
        }
    }
}

// ---------------- conv GEMM (BK=32, split-A 2-product; unchanged) ----------------
#define GSTR 40
#define TILEB (128 * GSTR * 2)
#define CSTG (3 * TILEB)
#define CSMTOT (3 * CSTG)     // 92160 B/CTA

__global__ void __launch_bounds__(256, 2)
conv_gemm(const __half* __restrict__ Ah, const __half* __restrict__ Al,
          const __half* __restrict__ Wh, const float* __restrict__ bias,
          const float* __restrict__ pos, float* __restrict__ hout) {
    extern __shared__ char dsm[];
    const uint32_t sb = smem_u32(dsm);
    const int K = KCPAD, KT = KCPAD / 32;  // 20

    const int tid = threadIdx.x;
    const int lane = tid & 31, wid = tid >> 5;
    const int wm = wid & 1, wn = wid >> 1;
    const int group = lane >> 2, tq = lane & 3;
    const int m0 = blockIdx.y * 128;
    const int n0 = blockIdx.x * 128;

    const __half* gAh = Ah + (size_t)m0 * K;
    const __half* gAl = Al + (size_t)m0 * K;
    const __half* gWh = Wh + (size_t)n0 * K;

    float acc[4][4][4];
#pragma unroll
    for (int mi = 0; mi < 4; mi++)
#pragma unroll
        for (int ni = 0; ni < 4; ni++)
#pragma unroll
            for (int q = 0; q < 4; q++) acc[mi][ni][q] = 0.f;

    const int lr = tid >> 2;
    const int lc = tid & 3;

    auto load_stage = [&](int kt, int st) {
        const size_t koff = (size_t)kt * 32;
        uint32_t base = sb + st * CSTG;
#pragma unroll
        for (int i = 0; i < 2; i++) {
            int r = lr + i * 64;
            uint32_t so = (r * GSTR + lc * 8) * 2;
            size_t go = (size_t)r * K + koff + lc * 8;
            cp_async16(base + 0 * TILEB + so, gAh + go);
            cp_async16(base + 1 * TILEB + so, gAl + go);
            cp_async16(base + 2 * TILEB + so, gWh + go);
        }
        cp_commit();
    };

    const uint32_t arow = wm * 64 + (lane & 7) + ((lane >> 3) & 1) * 8;
    const uint32_t acol = (lane >> 4) * 8;
    const uint32_t aoff = (arow * GSTR + acol) * 2;
    const uint32_t brow = wn * 32 + (lane & 7) + (lane >> 4) * 8;
    const uint32_t bcol = ((lane >> 3) & 1) * 8;
    const uint32_t boff = (brow * GSTR + bcol) * 2;

    load_stage(0, 0);
    load_stage(1, 1);

#pragma unroll 1
    for (int kt = 0; kt < KT; kt++) {
        if (kt + 1 < KT) cp_wait<1>();
        else             cp_wait<0>();
        __syncthreads();

        const uint32_t stbase = sb + (kt % 3) * CSTG;
        const uint32_t aH = stbase + aoff;
        const uint32_t aL = stbase + TILEB + aoff;
        const uint32_t bH = stbase + 2 * TILEB + boff;

#pragma unroll
        for (int ks = 0; ks < 2; ks++) {
            const uint32_t kadd = ks * 32;
            uint32_t afh[16], afl[16], bh[8];
#pragma unroll
            for (int mi = 0; mi < 4; mi++) {
                ldsm4(afh + mi * 4, aH + mi * (16 * GSTR * 2) + kadd);
                ldsm4(afl + mi * 4, aL + mi * (16 * GSTR * 2) + kadd);
            }
#pragma unroll
            for (int nj = 0; nj < 2; nj++)
                ldsm4(bh + nj * 4, bH + nj * (16 * GSTR * 2) + kadd);
#pragma unroll
            for (int mi = 0; mi < 4; mi++)
#pragma unroll
                for (int ni = 0; ni < 4; ni++)
                    mma_f16(acc[mi][ni], afh + mi * 4, bh + ni * 2);
#pragma unroll
            for (int mi = 0; mi < 4; mi++)
#pragma unroll
                for (int ni = 0; ni < 4; ni++)
                    mma_f16(acc[mi][ni], afl + mi * 4, bh + ni * 2);
        }

        if (kt + 2 < KT) load_stage(kt + 2, (kt + 2) % 3);
    }

#pragma unroll
    for (int mi = 0; mi < 4; mi++) {
#pragma unroll
        for (int rr = 0; rr < 2; rr++) {
            int m = m0 + wm * 64 + mi * 16 + group + rr * 8;
            int b = m / NPATCH, p = m % NPATCH;
            size_t row = (size_t)b * NTOK + p + 1;
            const float* pr = pos + (size_t)(p + 1) * DD;
#pragma unroll
            for (int ni = 0; ni < 4; ni++) {
                int n = n0 + wn * 32 + ni * 8 + tq * 2;
                float v0 = acc[mi][ni][rr * 2 + 0] + bias[n] + pr[n];
                float v1 = acc[mi][ni][rr * 2 + 1] + bias[n + 1] + pr[n + 1];
                *(float2*)(hout + row * DD + n) = make_float2(v0, v1);
            }
        }
    }
}

// ---------------- im2col -> split fp16 (padded K=640) ----------------
__global__ void im2col_split(const float* __restrict__ x,
                             __half* __restrict__ colh, __half* __restrict__ coll) {
    int idx = blockIdx.x * blockDim.x + threadIdx.x;
    if (idx >= CROWS * KCPAD) return;
    int r = idx / KCPAD, c = idx % KCPAD;
    float v = 0.f;
    if (c < KCONV) {
        int b = r / NPATCH, p = r % NPATCH;
        int chn = c / 100, rem = c % 100;
        int kh = rem / 10, kw = rem % 10;
        int phh = p / 34, pw = p % 34;
        v = x[((b * 6 + chn) * 50 + phh * 10 + kh) * 345 + pw * 10 + kw];
    }
    __half hi, lo;
    splith(v, hi, lo);
    colh[idx] = hi;
    coll[idx] = lo;
}

// ---------------- conv weight -> fp16 (padded K=640) ----------------
__global__ void convw_prep(const float* __restrict__ w, __half* __restrict__ wh) {
    int idx = blockIdx.x * blockDim.x + threadIdx.x;
    if (idx >= DD * KCPAD) return;
    int d = idx / KCPAD, k = idx % KCPAD;
    wh[idx] = __float2half(k < KCONV ? w[d * KCONV + k] : 0.f);
}

// ---------------- cls token rows ----------------
__global__ void cls_fill(const float* __restrict__ cls, const float* __restrict__ pos,
                         float* __restrict__ h) {
    int idx = blockIdx.x * blockDim.x + threadIdx.x;
    if (idx >= BATCH * DD) return;
    int b = idx / DD, d = idx % DD;
    h[(size_t)b * NTOK * DD + d] = cls[d] + pos[d];
}

// ---------------- weight transpose -> fp16 (hi only) ----------------
__global__ void transpose_hi(const float* __restrict__ W, __half* __restrict__ Wh,
                             int R, int C) {
    __shared__ float t[32][33];
    int z = blockIdx.z;
    const float* Wz = W + (size_t)z * R * C;
    __half* Whz = Wh + (size_t)z * R * C;
    int c0 = blockIdx.x * 32, r0 = blockIdx.y * 32;
    int x = threadIdx.x, y = threadIdx.y;
#pragma unroll
    for (int i = 0; i < 32; i += 8)
        t[y + i][x] = Wz[(size_t)(r0 + y + i) * C + c0 + x];
    __syncthreads();
#pragma unroll
    for (int i = 0; i < 32; i += 8)
        Whz[(size_t)(c0 + y + i) * R + r0 + x] = __float2half(t[x][y + i]);
}

// ---------------- LayerNorm fp32 -> fp16 ----------------
__global__ void ln_f16_kernel(const float* __restrict__ X, const float* __restrict__ w,
                              const float* __restrict__ b, __half* __restrict__ Y) {
    int row = blockIdx.x;
    int tid = threadIdx.x;
    const float* xr = X + (size_t)row * DD;
    float v0 = xr[tid], v1 = xr[tid + 256], v2 = xr[tid + 512];
    float s = v0 + v1 + v2;
    float q = v0 * v0 + v1 * v1 + v2 * v2;
    int lane = tid & 31, warp = tid >> 5;
#pragma unroll
    for (int off = 16; off; off >>= 1) {
        s += __shfl_down_sync(0xffffffffu, s, off);
        q += __shfl_down_sync(0xffffffffu, q, off);
    }
    __shared__ float sa[8], sbm[8];
    if (lane == 0) { sa[warp] = s; sbm[warp] = q; }
    __syncthreads();
    if (warp == 0) {
        s = (lane < 8) ? sa[lane] : 0.f;
        q = (lane < 8) ? sbm[lane] : 0.f;
#pragma unroll
        for (int off = 4; off; off >>= 1) {
            s += __shfl_down_sync(0xffffffffu, s, off);
            q += __shfl_down_sync(0xffffffffu, q, off);
        }
        if (lane == 0) { sa[0] = s; sbm[0] = q; }
    }
    __syncthreads();
    float mean = sa[0] * (1.f / DD);
    float var = sbm[0] * (1.f / DD) - mean * mean;
    float inv = rsqrtf(var + EPS);
    __half* yr = Y + (size_t)row * DD;
    yr[tid]       = __float2half((v0 - mean) * inv * w[tid]       + b[tid]);
    yr[tid + 256] = __float2half((v1 - mean) * inv * w[tid + 256] + b[tid + 256]);
    yr[tid + 512] = __float2half((v2 - mean) * inv * w[tid + 512] + b[tid + 512]);
}

// ---------------- LayerNorm fp32 -> fp32 (final, cls rows) ----------------
__global__ void ln_kernel(const float* __restrict__ X, const float* __restrict__ w,
                          const float* __restrict__ b, float* __restrict__ Y, int row_mul) {
    int row_in = blockIdx.x * row_mul;
    int row_out = blockIdx.x;
    int tid = threadIdx.x;
    const float* xr = X + (size_t)row_in * DD;
    float v0 = xr[tid], v1 = xr[tid + 256], v2 = xr[tid + 512];
    float s = v0 + v1 + v2;
    float q = v0 * v0 + v1 * v1 + v2 * v2;
    int lane = tid & 31, warp = tid >> 5;
#pragma unroll
    for (int off = 16; off; off >>= 1) {
        s += __shfl_down_sync(0xffffffffu, s, off);
        q += __shfl_down_sync(0xffffffffu, q, off);
    }
    __shared__ float sa[8], sbm[8];
    if (lane == 0) { sa[warp] = s; sbm[warp] = q; }
    __syncthreads();
    if (warp == 0) {
        s = (lane < 8) ? sa[lane] : 0.f;
        q = (lane < 8) ? sbm[lane] : 0.f;
#pragma unroll
        for (int off = 4; off; off >>= 1) {
            s += __shfl_down_sync(0xffffffffu, s, off);
            q += __shfl_down_sync(0xffffffffu, q, off);
        }
        if (lane == 0) { sa[0] = s; sbm[0] = q; }
    }
    __syncthreads();
    float mean = sa[0] * (1.f / DD);
    float var = sbm[0] * (1.f / DD) - mean * mean;
    float inv = rsqrtf(var + EPS);
    float* yr = Y + (size_t)row_out * DD;
    yr[tid]       = (v0 - mean) * inv * w[tid]       + b[tid];
    yr[tid + 256] = (v1 - mean) * inv * w[tid + 256] + b[tid + 256];
    yr[tid + 512] = (v2 - mean) * inv * w[tid + 512] + b[tid + 512];
}

// ---------------- MMA attention (fp16 qkv in, single product, 11 warps) ----------------
#define NTOKP 176
#define ASTR 72
#define VSTR 184
#define SA_QH 0
#define SA_KH (SA_QH + NTOKP*ASTR*2)
#define SA_VH (SA_KH + NTOKP*ASTR*2)
#define ATTN_SMEM (SA_VH + 64*VSTR*2)   // 74240 B
#define ATHREADS 352

__global__ void __launch_bounds__(ATHREADS, 1)
attn_mma_kernel(const __half* __restrict__ qkv, __half* __restrict__ out) {
    extern __shared__ char asmem[];
    const uint32_t sb = smem_u32(asmem);
    __half* QH = (__half*)(asmem + SA_QH);
    __half* KH = (__half*)(asmem + SA_KH);
    __half* VH = (__half*)(asmem + SA_VH);

    const int bh = blockIdx.x;
    const int b = bh / NHEAD, hh = bh % NHEAD;
    const int tid = threadIdx.x;
    const int lane = tid & 31, wid = tid >> 5;
    const int group = lane >> 2, tq = lane & 3;
    const size_t base = (size_t)b * NTOK * (3 * DD) + hh * HDIM;

    // vectorized fill: each iteration handles 2 contiguous d values
    for (int idx = tid; idx < NTOKP * 32; idx += ATHREADS) {
        int row = idx >> 5, d = (idx & 31) * 2;
        __half2 qv = __floats2half2_rn(0.f, 0.f), kv = qv, vv = qv;
        if (row < NTOK) {
            size_t o = base + (size_t)row * (3 * DD) + d;
            qv = *(const __half2*)(qkv + o);
            kv = *(const __half2*)(qkv + o + DD);
            vv = *(const __half2*)(qkv + o + 2 * DD);
        }
        *(__half2*)(QH + row * ASTR + d) = qv;
        *(__half2*)(KH + row * ASTR + d) = kv;
        VH[d * VSTR + row] = __low2half(vv);
        VH[(d + 1) * VSTR + row] = __high2half(vv);
    }
    __syncthreads();

    const uint32_t a_r = (lane & 7) + ((lane >> 3) & 1) * 8;
    const uint32_t a_c = (lane >> 4) * 8;
    const uint32_t b_r = (lane & 7) + (lane >> 4) * 8;
    const uint32_t b_c = ((lane >> 3) & 1) * 8;

    if (wid < 11) {
        const int m0 = wid * 16;

        uint32_t aq[4][4];
#pragma unroll
        for (int k = 0; k < 4; k++) {
            uint32_t off = ((m0 + a_r) * ASTR + a_c + k * 16) * 2;
            ldsm4(aq[k], sb + SA_QH + off);
        }

        float s[22][4];
#pragma unroll
        for (int j = 0; j < 22; j++)
#pragma unroll
            for (int q = 0; q < 4; q++) s[j][q] = 0.f;

#pragma unroll
        for (int nj = 0; nj < 11; nj++) {
            const int n0 = nj * 16;
#pragma unroll
            for (int k = 0; k < 4; k++) {
                uint32_t bkh[4];
                uint32_t off = ((n0 + b_r) * ASTR + b_c + k * 16) * 2;
                ldsm4(bkh, sb + SA_KH + off);
                mma_f16(s[2 * nj],     aq[k], bkh);
                mma_f16(s[2 * nj + 1], aq[k], bkh + 2);
            }
        }

        {
            int c0 = 168 + tq * 2;
            if (c0 >= NTOK)     { s[21][0] = -1e30f; s[21][2] = -1e30f; }
            if (c0 + 1 >= NTOK) { s[21][1] = -1e30f; s[21][3] = -1e30f; }
        }

        float mx0 = -1e30f, mx1 = -1e30f;
#pragma unroll
        for (int j = 0; j < 22; j++) {
            mx0 = fmaxf(mx0, fmaxf(s[j][0], s[j][1]));
            mx1 = fmaxf(mx1, fmaxf(s[j][2], s[j][3]));
        }
        mx0 = fmaxf(mx0, __shfl_xor_sync(0xffffffffu, mx0, 1));
        mx0 = fmaxf(mx0, __shfl_xor_sync(0xffffffffu, mx0, 2));
        mx1 = fmaxf(mx1, __shfl_xor_sync(0xffffffffu, mx1, 1));
        mx1 = fmaxf(mx1, __shfl_xor_sync(0xffffffffu, mx1, 2));

        float rs0 = 0.f, rs1 = 0.f;
#pragma unroll
        for (int j = 0; j < 22; j++) {
            s[j][0] = __expf((s[j][0] - mx0) * 0.125f);
            s[j][1] = __expf((s[j][1] - mx0) * 0.125f);
            s[j][2] = __expf((s[j][2] - mx1) * 0.125f);
            s[j][3] = __expf((s[j][3] - mx1) * 0.125f);
            rs0 += s[j][0] + s[j][1];
            rs1 += s[j][2] + s[j][3];
        }
        rs0 += __shfl_xor_sync(0xffffffffu, rs0, 1);
        rs0 += __shfl_xor_sync(0xffffffffu, rs0, 2);
        rs1 += __shfl_xor_sync(0xffffffffu, rs1, 1);
        rs1 += __shfl_xor_sync(0xffffffffu, rs1, 2);

        float o[8][4];
#pragma unroll
        for (int j = 0; j < 8; j++)
#pragma unroll
            for (int q = 0; q < 4; q++) o[j][q] = 0.f;

#pragma unroll
        for (int kt = 0; kt < 11; kt++) {
            uint32_t ap[4];
#pragma unroll
            for (int half = 0; half < 2; half++) {
                const float* sv = s[2 * kt + half];
                ap[2 * half]     = pack_h2(sv[0], sv[1]);
                ap[2 * half + 1] = pack_h2(sv[2], sv[3]);
            }
#pragma unroll
            for (int dj = 0; dj < 4; dj++) {
                const int d0 = dj * 16;
                uint32_t bvh[4];
                uint32_t off = ((d0 + b_r) * VSTR + b_c + kt * 16) * 2;
                ldsm4(bvh, sb + SA_VH + off);
                mma_f16(o[2 * dj],     ap, bvh);
                mma_f16(o[2 * dj + 1], ap, bvh + 2);
            }
        }

        const float i0 = 1.f / rs0, i1 = 1.f / rs1;
        const int r0 = m0 + group, r1 = r0 + 8;
#pragma unroll
        for (int j = 0; j < 8; j++) {
            int d = 8 * j + tq * 2;
            if (r0 < NTOK) {
                __half2 hv = __floats2half2_rn(o[j][0] * i0, o[j][1] * i0);
                *(__half2*)(out + (size_t)(b * NTOK + r0) * DD + hh * HDIM + d) = hv;
            }
            if (r1 < NTOK) {
                __half2 hv = __floats2half2_rn(o[j][2] * i1, o[j][3] * i1);
                *(__half2*)(out + (size_t)(b * NTOK + r1) * DD + hh * HDIM + d) = hv;
            }
        }
    }
}

// ---------------- head ----------------
__global__ void head_kernel(const float* __restrict__ cls, const float* __restrict__ hw,
                            const float* __restrict__ hb, float* __restrict__ out) {
    int b = blockIdx.x;
    int tid = threadIdx.x;
    float a0 = 0.f, a1 = 0.f, a2 = 0.f;
    for (int d = tid; d < DD; d += 256) {
        float v = cls[b * DD + d];
        a0 += v * hw[d * 3 + 0];
        a1 += v * hw[d * 3 + 1];
        a2 += v * hw[d * 3 + 2];
    }
    int lane = tid & 31, warp = tid >> 5;
#pragma unroll
    for (int off = 16; off; off >>= 1) {
        a0 += __shfl_down_sync(0xffffffffu, a0, off);
        a1 += __shfl_down_sync(0xffffffffu, a1, off);
        a2 += __shfl_down_sync(0xffffffffu, a2, off);
    }
    __shared__ float s0[8], s1[8], s2[8];
    if (lane == 0) { s0[warp] = a0; s1[warp] = a1; s2[warp] = a2; }
    __syncthreads();
    if (warp == 0 && lane < 8) {
        a0 = s0[lane]; a1 = s1[lane]; a2 = s2[lane];
#pragma unroll
        for (int off = 4; off; off >>= 1) {
            a0 += __shfl_down_sync(0x000000ffu, a0, off);
            a1 += __shfl_down_sync(0x000000ffu, a1, off);
            a2 += __shfl_down_sync(0x000000ffu, a2, off);
        }
        if (lane == 0) {
            out[b * 3 + 0] = a0 + hb[0];
            out[b * 3 + 1] = a1 + hb[1];
            out[b * 3 + 2] = a2 + hb[2];
        }
    }
}

// ---------------- launcher ----------------
extern "C" void kernel_launch(void* const* d_in, const int* in_sizes, int n_in,
                              void* d_out, int out_size) {
    const float* x        = (const float*)d_in[0];
    const float* conv_w   = (const float*)d_in[1];
    const float* conv_b   = (const float*)d_in[2];
    const float* cls_tok  = (const float*)d_in[3];
    const float* pos      = (const float*)d_in[4];
    const float* ln1_w    = (const float*)d_in[5];
    const float* ln1_b    = (const float*)d_in[6];
    const float* qkv_w    = (const float*)d_in[7];
    const float* qkv_b    = (const float*)d_in[8];
    const float* proj_w   = (const float*)d_in[9];
    const float* proj_b   = (const float*)d_in[10];
    const float* ln2_w    = (const float*)d_in[11];
    const float* ln2_b    = (const float*)d_in[12];
    const float* fc1_w    = (const float*)d_in[13];
    const float* fc1_b    = (const float*)d_in[14];
    const float* fc2_w    = (const float*)d_in[15];
    const float* fc2_b    = (const float*)d_in[16];
    const float* norm_w   = (const float*)d_in[17];
    const float* norm_b   = (const float*)d_in[18];
    const float* head_w   = (const float*)d_in[19];
    const float* head_b   = (const float*)d_in[20];
    float* out = (float*)d_out;

    float *h, *clsb;
    __half *colh, *coll, *convWh, *qkvh, *yf, *af, *bigf;
    __half *qkvWh, *projWh, *fc1Wh, *fc2Wh;
    cudaGetSymbolAddress((void**)&colh, g_colh);
    cudaGetSymbolAddress((void**)&coll, g_coll);
    cudaGetSymbolAddress((void**)&convWh, g_convWh);
    cudaGetSymbolAddress((void**)&h, g_h);
    cudaGetSymbolAddress((void**)&clsb, g_cls);
    cudaGetSymbolAddress((void**)&qkvh, g_qkvh);
    cudaGetSymbolAddress((void**)&yf, g_yf);
    cudaGetSymbolAddress((void**)&af, g_af);
    cudaGetSymbolAddress((void**)&bigf, g_bigf);
    cudaGetSymbolAddress((void**)&qkvWh, g_qkvWh);
    cudaGetSymbolAddress((void**)&projWh, g_projWh);
    cudaGetSymbolAddress((void**)&fc1Wh, g_fc1Wh);
    cudaGetSymbolAddress((void**)&fc2Wh, g_fc2Wh);

    cudaFuncSetAttribute(attn_mma_kernel, cudaFuncAttributeMaxDynamicSharedMemorySize, ATTN_SMEM);
    cudaFuncSetAttribute(hmma_gemm<true, false, false>, cudaFuncAttributeMaxDynamicSharedMemorySize, SMTOT1);
    cudaFuncSetAttribute(hmma_gemm<false, false, true>, cudaFuncAttributeMaxDynamicSharedMemorySize, SMTOT1);
    cudaFuncSetAttribute(hmma_gemm<true, true, false>, cudaFuncAttributeMaxDynamicSharedMemorySize, SMTOT1);
    cudaFuncSetAttribute(conv_gemm, cudaFuncAttributeMaxDynamicSharedMemorySize, CSMTOT);

    // weight prep
    transpose_hi<<<dim3(3 * DD / 32, DD / 32, DEPTH), dim3(32, 8)>>>(qkv_w, qkvWh, DD, 3 * DD);
    transpose_hi<<<dim3(DD / 32, DD / 32, DEPTH), dim3(32, 8)>>>(proj_w, projWh, DD, DD);
    transpose_hi<<<dim3(4 * DD / 32, DD / 32, DEPTH), dim3(32, 8)>>>(fc1_w, fc1Wh, DD, 4 * DD);
    transpose_hi<<<dim3(DD / 32, 4 * DD / 32, DEPTH), dim3(32, 8)>>>(fc2_w, fc2Wh, 4 * DD, DD);
    convw_prep<<<(DD * KCPAD + 255) / 256, 256>>>(conv_w, convWh);

    // patch embed (fp16 2-product, fused pos-embed + assemble)
    im2col_split<<<(CROWS * KCPAD + 255) / 256, 256>>>(x, colh, coll);
    cls_fill<<<(BATCH * DD + 255) / 256, 256>>>(cls_tok, pos, h);
    conv_gemm<<<dim3(DD / 128, CROWS / 128), 256, CSMTOT>>>(colh, coll, convWh, conv_b, pos, h);

    const int MT = MPAD / 128;  // 86
    for (int i = 0; i < DEPTH; i++) {
        ln_f16_kernel<<<MROWS, 256>>>(h, ln1_w + (size_t)i * DD, ln1_b + (size_t)i * DD, yf);
        hmma_gemm<true, false, false><<<dim3(3 * DD / 128, MT), 256, SMTOT1>>>(
            yf, qkvWh + (size_t)i * 3 * DD * DD,
            qkv_b + (size_t)i * 3 * DD, nullptr, nullptr, qkvh, MROWS, 3 * DD, DD);
        attn_mma_kernel<<<BATCH * NHEAD, ATHREADS, ATTN_SMEM>>>(qkvh, af);
        hmma_gemm<false, false, true><<<dim3(DD / 128, MT), 256, SMTOT1>>>(
            af, projWh + (size_t)i * DD * DD,
            proj_b + (size_t)i * DD, h, h, nullptr, MROWS, DD, DD);
        ln_f16_kernel<<<MROWS, 256>>>(h, ln2_w + (size_t)i * DD, ln2_b + (size_t)i * DD, yf);
        hmma_gemm<true, true, false><<<dim3(4 * DD / 128, MT), 256, SMTOT1>>>(
            yf, fc1Wh + (size_t)i * 4 * DD * DD,
            fc1_b + (size_t)i * 4 * DD, nullptr, nullptr, bigf, MROWS, 4 * DD, DD);
        hmma_gemm<false, false, true><<<dim3(DD / 128, MT), 256, SMTOT1>>>(
            bigf, fc2Wh + (size_t)i * 4 * DD * DD,
            fc2_b + (size_t)i * DD, h, h, nullptr, MROWS, DD, 4 * DD);
    }

    ln_kernel<<<BATCH, 256>>>(h, norm_w, norm_b, clsb, NTOK);
    head_kernel<<<BATCH, 256>>>(clsb, head_w, head_b, out);
}